// round 11
// baseline (speedup 1.0000x reference)
#include <cuda_runtime.h>

// ---------------------------------------------------------------------------
// Att_mask, one warp per batch item (lane = rank r), packed f32x2 FFMA.
// R9 -> R10 changes (LSU-pipe was binding at 83%):
//  - A matrices packed as float4 (aq,ak,av,0):  1 LDS.128/d instead of 3 LDS.32
//  - K/V rows stride 20 floats (16B aligned) -> 4 LDS.128 per row in scores
//    loop (was 8 LDS.64); writes chunk-rotated by (row>>3)&3 for conflict-free
//    STS.128, un-rotated at read with compile-time indices.
//  - sK/sV alias the x staging buffer (x dead after projection): smem 94->74KB
//  - vectorized publish / halved reduction loads
// ---------------------------------------------------------------------------

typedef unsigned long long u64;

__device__ __forceinline__ u64 ff2(u64 a, u64 b, u64 c) {
    u64 d; asm("fma.rn.f32x2 %0, %1, %2, %3;" : "=l"(d) : "l"(a), "l"(b), "l"(c)); return d;
}
__device__ __forceinline__ u64 mul2(u64 a, u64 b) {
    u64 d; asm("mul.rn.f32x2 %0, %1, %2;" : "=l"(d) : "l"(a), "l"(b)); return d;
}
__device__ __forceinline__ u64 dup2(float a) {
    u64 d; asm("mov.b64 %0, {%1, %1};" : "=l"(d) : "f"(a)); return d;
}
__device__ __forceinline__ float2 un2(u64 a) {
    float2 f; asm("mov.b64 {%0, %1}, %2;" : "=f"(f.x), "=f"(f.y) : "l"(a)); return f;
}
__device__ __forceinline__ u64 pk2(float x, float y) {
    u64 d; asm("mov.b64 %0, {%1, %2};" : "=l"(d) : "f"(x), "f"(y)); return d;
}
__device__ __forceinline__ float tanh_approx(float x) {
    float y; asm("tanh.approx.f32 %0, %1;" : "=f"(y) : "f"(x)); return y;
}

static constexpr int WARPS = 8;     // warps per block
static constexpr int NB    = 4;     // batch items per warp
// shared layout (floats):
//   sA4: float4[64][32]  (aq,ak,av,0)               = 8192 floats
//   sAo: [32]                                       =   32
//   per warp: 1280-float region, used as
//       x[64][16] (1024) during projection, then aliased by
//       K rows [32] stride 20 (640) + V rows [32] stride 20 (640)
static constexpr int A4_FLOATS = 64 * 32 * 4;                     // 8192
static constexpr int A_TOT     = A4_FLOATS + 32;                  // 8224
static constexpr int PW_FLOATS = 1280;
static constexpr int SMEM_BYTES = (A_TOT + WARPS * PW_FLOATS) * 4; // 73856

__global__ void __launch_bounds__(WARPS * 32, 2)
att_mask_kernel(const float* __restrict__ x, const float* __restrict__ L,
                const float* __restrict__ Aq, const float* __restrict__ Ak,
                const float* __restrict__ Av, const float* __restrict__ Ao,
                float* __restrict__ out)
{
    extern __shared__ float smem[];
    float4* sA4 = (float4*)smem;          // [64][32]
    float*  sAo = smem + A4_FLOATS;       // [32]

    const int tid = threadIdx.x;

    // A packed+transposed: sA4[d*32+r] = (Aq[r][d], Ak[r][d], Av[r][d], 0)
    for (int i = tid; i < 2048; i += WARPS * 32) {
        int d = i >> 5, r = i & 31;
        sA4[i] = make_float4(Aq[r * 64 + d], Ak[r * 64 + d], Av[r * 64 + d], 0.f);
    }
    if (tid < 32) sAo[tid] = Ao[tid];
    __syncthreads();

    const int w    = tid >> 5;
    const int lane = tid & 31;

    float* sx = smem + A_TOT + w * PW_FLOATS;   // [64][16] during projection
    float* sK = sx;                             // aliased: 32 rows, stride 20
    float* sV = sx + 640;

    const float aor  = sAo[lane];
    const int   rotw = (lane >> 3) & 3;         // write-rotation for this row

    for (int jj = 0; jj < NB; jj++) {
        const int b = (blockIdx.x * WARPS + w) * NB + jj;

        // --- stage x_b (64x16 fp32 = 4KB contiguous) into shared ---
        {
            const float4* xg = (const float4*)(x + (size_t)b * 1024);
            float4* xs = (float4*)sx;
            #pragma unroll
            for (int i = 0; i < 8; i++)
                xs[i * 32 + lane] = xg[i * 32 + lane];
        }

        // --- num_neighbors from L[b,0,:] (values are exactly 0.0/1.0) ---
        float Lv = (lane < 16) ? L[(size_t)b * 256 + lane] : 0.0f;
        unsigned msk = __ballot_sync(0xffffffffu, Lv >= 1.0f);
        float rs = rsqrtf((float)(__popc(msk) + 1));
        __syncwarp();

        // --- projections: lane r accumulates Q/K/V row r over d, packed x2 ---
        u64 q[8], k[8], v[8];
        #pragma unroll
        for (int p = 0; p < 8; p++) { q[p] = 0ull; k[p] = 0ull; v[p] = 0ull; }

        #pragma unroll 4
        for (int d = 0; d < 64; d++) {
            const ulonglong2* xr = (const ulonglong2*)(sx + d * 16);
            ulonglong2 xa = xr[0], xb = xr[1], xc = xr[2], xd = xr[3];
            float4 a4 = sA4[d * 32 + lane];           // 1 LDS.128, conflict-free
            u64 aq = dup2(a4.x);
            u64 ak = dup2(a4.y);
            u64 av = dup2(a4.z);
            q[0] = ff2(aq, xa.x, q[0]); q[1] = ff2(aq, xa.y, q[1]);
            q[2] = ff2(aq, xb.x, q[2]); q[3] = ff2(aq, xb.y, q[3]);
            q[4] = ff2(aq, xc.x, q[4]); q[5] = ff2(aq, xc.y, q[5]);
            q[6] = ff2(aq, xd.x, q[6]); q[7] = ff2(aq, xd.y, q[7]);
            k[0] = ff2(ak, xa.x, k[0]); k[1] = ff2(ak, xa.y, k[1]);
            k[2] = ff2(ak, xb.x, k[2]); k[3] = ff2(ak, xb.y, k[3]);
            k[4] = ff2(ak, xc.x, k[4]); k[5] = ff2(ak, xc.y, k[5]);
            k[6] = ff2(ak, xd.x, k[6]); k[7] = ff2(ak, xd.y, k[7]);
            v[0] = ff2(av, xa.x, v[0]); v[1] = ff2(av, xa.y, v[1]);
            v[2] = ff2(av, xb.x, v[2]); v[3] = ff2(av, xb.y, v[3]);
            v[4] = ff2(av, xc.x, v[4]); v[5] = ff2(av, xc.y, v[5]);
            v[6] = ff2(av, xd.x, v[6]); v[7] = ff2(av, xd.y, v[7]);
        }
        __syncwarp();   // all lanes done reading sx; safe to overwrite with K/V

        // --- tanh; fold 1/sqrt(nn) into Q; publish K,V rows (chunk-rotated) ---
        {
            u64 rs2 = dup2(rs);
            #pragma unroll
            for (int p = 0; p < 8; p++) {
                float2 fq = un2(q[p]);
                q[p] = mul2(pk2(tanh_approx(fq.x), tanh_approx(fq.y)), rs2);
                float2 fk = un2(k[p]);
                k[p] = pk2(tanh_approx(fk.x), tanh_approx(fk.y));
                float2 fv = un2(v[p]);
                v[p] = pk2(tanh_approx(fv.x), tanh_approx(fv.y));
            }
            ulonglong2* kw = (ulonglong2*)(sK + lane * 20);
            ulonglong2* vw = (ulonglong2*)(sV + lane * 20);
            #pragma unroll
            for (int c = 0; c < 4; c++) {
                int pc = (c + rotw) & 3;   // rotated position: conflict-free STS.128
                kw[pc] = make_ulonglong2(k[2 * c], k[2 * c + 1]);
                vw[pc] = make_ulonglong2(v[2 * c], v[2 * c + 1]);
            }
        }
        __syncwarp();

        // --- fused scores + softmax-numerator + o accumulation ---
        // |score| <= 16 -> exp safe without max subtraction.
        u64 o[8];
        #pragma unroll
        for (int p = 0; p < 8; p++) o[p] = 0ull;
        float esum = 0.0f;

        #pragma unroll
        for (int s8 = 0; s8 < 4; s8++) {          // rows s8*8 .. s8*8+7 share rotation s8
            #pragma unroll
            for (int t = 0; t < 8; t++) {
                const int s = s8 * 8 + t;
                const ulonglong2* kr = (const ulonglong2*)(sK + s * 20);
                u64 acc = 0ull;
                #pragma unroll
                for (int p = 0; p < 4; p++) {
                    const int c = (p + 4 - s8) & 3;   // logical chunk at position p
                    ulonglong2 kk = kr[p];
                    acc = ff2(q[2 * c],     kk.x, acc);
                    acc = ff2(q[2 * c + 1], kk.y, acc);
                }
                float2 a2 = un2(acc);
                float e = __expf(a2.x + a2.y);
                esum += e;
                u64 e2 = dup2(e);
                const ulonglong2* vr = (const ulonglong2*)(sV + s * 20);
                #pragma unroll
                for (int p = 0; p < 4; p++) {
                    const int c = (p + 4 - s8) & 3;
                    ulonglong2 vv = vr[p];
                    o[2 * c]     = ff2(e2, vv.x, o[2 * c]);
                    o[2 * c + 1] = ff2(e2, vv.y, o[2 * c + 1]);
                }
            }
        }

        // --- contribution c[r][n] = (Ao[r]/esum) * o[r][n]; reduce over r ---
        float coef = __fdividef(aor, esum);
        u64 c2 = dup2(coef);
        __syncwarp();                       // everyone done reading sK rows
        {
            ulonglong2* cw = (ulonglong2*)(sK + lane * 20);  // plain layout
            #pragma unroll
            for (int c = 0; c < 4; c++)
                cw[c] = make_ulonglong2(mul2(c2, o[2 * c]), mul2(c2, o[2 * c + 1]));
        }
        __syncwarp();

        const int jn    = lane & 15;
        const int rbase = (lane >> 4) << 4;     // low lanes sum r=0..15, high r=16..31
        float cs0 = 0.0f, cs1 = 0.0f;
        #pragma unroll
        for (int r = 0; r < 16; r += 2) {
            cs0 += sK[(rbase + r) * 20 + jn];
            cs1 += sK[(rbase + r + 1) * 20 + jn];
        }
        float cs = cs0 + cs1;
        float z  = cs + __shfl_xor_sync(0xffffffffu, cs, 16);
        float Rv = tanhf(z);                // accurate: feeds output directly
        float R2 = Rv * Rv;

        float tot = R2;
        tot += __shfl_xor_sync(0xffffffffu, tot, 8);
        tot += __shfl_xor_sync(0xffffffffu, tot, 4);
        tot += __shfl_xor_sync(0xffffffffu, tot, 2);
        tot += __shfl_xor_sync(0xffffffffu, tot, 1);

        if (lane < 16)
            out[(size_t)b * 16 + jn] = (jn == (b & 15)) ? tot : -R2;
        __syncwarp();
    }
}

extern "C" void kernel_launch(void* const* d_in, const int* in_sizes, int n_in,
                              void* d_out, int out_size)
{
    const float* x  = (const float*)d_in[0];
    const float* L  = (const float*)d_in[1];
    const float* Aq = (const float*)d_in[2];
    const float* Ak = (const float*)d_in[3];
    const float* Av = (const float*)d_in[4];
    const float* Ao = (const float*)d_in[5];
    float* out = (float*)d_out;

    int B = in_sizes[0] / (64 * 16);          // 65536
    int blocks = B / (WARPS * NB);            // 2048

    cudaFuncSetAttribute(att_mask_kernel,
                         cudaFuncAttributeMaxDynamicSharedMemorySize, SMEM_BYTES);
    att_mask_kernel<<<blocks, WARPS * 32, SMEM_BYTES>>>(x, L, Aq, Ak, Av, Ao, out);
}

// round 12
// speedup vs baseline: 1.0459x; 1.0459x over previous
#include <cuda_runtime.h>

// ---------------------------------------------------------------------------
// Att_mask, one warp per batch item. R11 -> R12: L1 crossbar is return-byte
// bound (broadcasts deliver 32x redundant bytes). New lane mapping:
//   lane = (rp, nh): rp = lane>>1 in [0,16) -> rows {2rp, 2rp+1},
//                    nh = lane&1            -> n-half [nh*8, nh*8+8)
// Each lane reads only HALF an x row / K row / V row (32B instead of 64B),
// halving broadcast traffic in both the projection and the scores loop.
// Cross-half score sums via one u64 shfl_xor(1) per s. Epilogue reduction
// entirely in registers via shfl_xor tree (no shared round-trip).
// ---------------------------------------------------------------------------

typedef unsigned long long u64;

__device__ __forceinline__ u64 ff2(u64 a, u64 b, u64 c) {
    u64 d; asm("fma.rn.f32x2 %0, %1, %2, %3;" : "=l"(d) : "l"(a), "l"(b), "l"(c)); return d;
}
__device__ __forceinline__ u64 mul2(u64 a, u64 b) {
    u64 d; asm("mul.rn.f32x2 %0, %1, %2;" : "=l"(d) : "l"(a), "l"(b)); return d;
}
__device__ __forceinline__ u64 add2(u64 a, u64 b) {
    u64 d; asm("add.rn.f32x2 %0, %1, %2;" : "=l"(d) : "l"(a), "l"(b)); return d;
}
__device__ __forceinline__ u64 dup2(float a) {
    u64 d; asm("mov.b64 %0, {%1, %1};" : "=l"(d) : "f"(a)); return d;
}
__device__ __forceinline__ float2 un2(u64 a) {
    float2 f; asm("mov.b64 {%0, %1}, %2;" : "=f"(f.x), "=f"(f.y) : "l"(a)); return f;
}
__device__ __forceinline__ u64 pk2(float x, float y) {
    u64 d; asm("mov.b64 %0, {%1, %2};" : "=l"(d) : "f"(x), "f"(y)); return d;
}
__device__ __forceinline__ float tanh_approx(float x) {
    float y; asm("tanh.approx.f32 %0, %1;" : "=f"(y) : "f"(x)); return y;
}
__device__ __forceinline__ u64 shflx(u64 v, int m) {
    return __shfl_xor_sync(0xffffffffu, v, m);
}

static constexpr int WARPS = 8;     // warps per block
static constexpr int NB    = 4;     // batch items per warp
// shared layout (floats):
//   sA: [64][16] records of 8 floats: (Aq[2rp][d],Aq[2rp+1][d],
//        Ak[2rp][d],Ak[2rp+1][d],Av[2rp][d],Av[2rp+1][d],0,0)  = 8192 floats
//   per warp: 1280-float region: x[64][16] (1024) during projection,
//        then aliased by K rows [32] stride 20 (640) + V rows (640)
static constexpr int A_FLOATS  = 64 * 16 * 8;                      // 8192
static constexpr int PW_FLOATS = 1280;
static constexpr int SMEM_BYTES = (A_FLOATS + WARPS * PW_FLOATS) * 4;  // 73728

__global__ void __launch_bounds__(WARPS * 32, 2)
att_mask_kernel(const float* __restrict__ x, const float* __restrict__ L,
                const float* __restrict__ Aq, const float* __restrict__ Ak,
                const float* __restrict__ Av, const float* __restrict__ Ao,
                float* __restrict__ out)
{
    extern __shared__ float smem[];
    float* sA = smem;

    const int tid = threadIdx.x;

    // Pack A per (d, rp): one 32B record read by the two lanes of the pair.
    for (int i = tid; i < 1024; i += WARPS * 32) {
        int d = i >> 4, rp = i & 15;
        float* p = sA + i * 8;
        p[0] = Aq[(2 * rp) * 64 + d];  p[1] = Aq[(2 * rp + 1) * 64 + d];
        p[2] = Ak[(2 * rp) * 64 + d];  p[3] = Ak[(2 * rp + 1) * 64 + d];
        p[4] = Av[(2 * rp) * 64 + d];  p[5] = Av[(2 * rp + 1) * 64 + d];
        p[6] = 0.f;                    p[7] = 0.f;
    }
    __syncthreads();

    const int w    = tid >> 5;
    const int lane = tid & 31;
    const int rp   = lane >> 1;      // row pair: rows 2rp, 2rp+1
    const int nh   = lane & 1;       // n-half: columns nh*8 .. nh*8+7

    float* sx = smem + A_FLOATS + w * PW_FLOATS;   // [64][16] during projection
    float* sK = sx;                                // aliased: 32 rows, stride 20
    float* sV = sx + 640;

    const float2 ao2 = ((const float2*)Ao)[rp];    // Ao[2rp], Ao[2rp+1]

    for (int jj = 0; jj < NB; jj++) {
        const int b = (blockIdx.x * WARPS + w) * NB + jj;

        // --- stage x_b (64x16 fp32 = 4KB contiguous) into shared ---
        {
            const float4* xg = (const float4*)(x + (size_t)b * 1024);
            float4* xs = (float4*)sx;
            #pragma unroll
            for (int i = 0; i < 8; i++)
                xs[i * 32 + lane] = xg[i * 32 + lane];
        }

        // --- num_neighbors from L[b,0,:] (values are exactly 0.0/1.0) ---
        float Lv = (lane < 16) ? L[(size_t)b * 256 + lane] : 0.0f;
        unsigned msk = __ballot_sync(0xffffffffu, Lv >= 1.0f);
        float rs = rsqrtf((float)(__popc(msk) + 1));
        __syncwarp();

        // --- projections: lane accumulates rows {2rp,2rp+1} x half-n ---
        // q/k/v[0..3] = row 2rp (4 u64 = 8 n-vals), [4..7] = row 2rp+1
        u64 q[8], k[8], v[8];
        #pragma unroll
        for (int p = 0; p < 8; p++) { q[p] = 0ull; k[p] = 0ull; v[p] = 0ull; }

        const float* xbase = sx + nh * 8;
        #pragma unroll 4
        for (int d = 0; d < 64; d++) {
            const ulonglong2* xr = (const ulonglong2*)(xbase + d * 16);
            ulonglong2 xa = xr[0], xb = xr[1];                 // 32B half-row
            const float* ap = sA + (d * 16 + rp) * 8;
            const float4 qk  = *(const float4*)ap;             // aq0,aq1,ak0,ak1
            const float2 avv = *(const float2*)(ap + 4);       // av0,av1
            u64 aq0 = dup2(qk.x),  aq1 = dup2(qk.y);
            u64 ak0 = dup2(qk.z),  ak1 = dup2(qk.w);
            u64 av0 = dup2(avv.x), av1 = dup2(avv.y);
            q[0] = ff2(aq0, xa.x, q[0]); q[1] = ff2(aq0, xa.y, q[1]);
            q[2] = ff2(aq0, xb.x, q[2]); q[3] = ff2(aq0, xb.y, q[3]);
            q[4] = ff2(aq1, xa.x, q[4]); q[5] = ff2(aq1, xa.y, q[5]);
            q[6] = ff2(aq1, xb.x, q[6]); q[7] = ff2(aq1, xb.y, q[7]);
            k[0] = ff2(ak0, xa.x, k[0]); k[1] = ff2(ak0, xa.y, k[1]);
            k[2] = ff2(ak0, xb.x, k[2]); k[3] = ff2(ak0, xb.y, k[3]);
            k[4] = ff2(ak1, xa.x, k[4]); k[5] = ff2(ak1, xa.y, k[5]);
            k[6] = ff2(ak1, xb.x, k[6]); k[7] = ff2(ak1, xb.y, k[7]);
            v[0] = ff2(av0, xa.x, v[0]); v[1] = ff2(av0, xa.y, v[1]);
            v[2] = ff2(av0, xb.x, v[2]); v[3] = ff2(av0, xb.y, v[3]);
            v[4] = ff2(av1, xa.x, v[4]); v[5] = ff2(av1, xa.y, v[5]);
            v[6] = ff2(av1, xb.x, v[6]); v[7] = ff2(av1, xb.y, v[7]);
        }
        __syncwarp();   // done reading sx; safe to overwrite with K/V

        // --- tanh; fold 1/sqrt(nn) into Q; publish K,V half-rows ---
        {
            u64 rs2 = dup2(rs);
            #pragma unroll
            for (int p = 0; p < 8; p++) {
                float2 fq = un2(q[p]);
                q[p] = mul2(pk2(tanh_approx(fq.x), tanh_approx(fq.y)), rs2);
                float2 fk = un2(k[p]);
                k[p] = pk2(tanh_approx(fk.x), tanh_approx(fk.y));
                float2 fv = un2(v[p]);
                v[p] = pk2(tanh_approx(fv.x), tanh_approx(fv.y));
            }
            const int r0 = 2 * rp, r1 = 2 * rp + 1;
            ulonglong2* k0p = (ulonglong2*)(sK + r0 * 20 + nh * 8);
            k0p[0] = make_ulonglong2(k[0], k[1]);
            k0p[1] = make_ulonglong2(k[2], k[3]);
            ulonglong2* k1p = (ulonglong2*)(sK + r1 * 20 + nh * 8);
            k1p[0] = make_ulonglong2(k[4], k[5]);
            k1p[1] = make_ulonglong2(k[6], k[7]);
            ulonglong2* v0p = (ulonglong2*)(sV + r0 * 20 + nh * 8);
            v0p[0] = make_ulonglong2(v[0], v[1]);
            v0p[1] = make_ulonglong2(v[2], v[3]);
            ulonglong2* v1p = (ulonglong2*)(sV + r1 * 20 + nh * 8);
            v1p[0] = make_ulonglong2(v[4], v[5]);
            v1p[1] = make_ulonglong2(v[6], v[7]);
        }
        __syncwarp();

        // --- fused scores + softmax numerator + o accumulation ---
        // |score| <= 16 -> exp safe without max subtraction.
        u64 o[8];
        #pragma unroll
        for (int p = 0; p < 8; p++) o[p] = 0ull;
        u64 esum2 = 0ull;    // packed (esum_r0, esum_r1)

        #pragma unroll 8
        for (int s = 0; s < 32; s++) {
            const ulonglong2* kr = (const ulonglong2*)(sK + s * 20 + nh * 8);
            ulonglong2 ka = kr[0], kb = kr[1];
            u64 a0 = mul2(q[0], ka.x); a0 = ff2(q[1], ka.y, a0);
            a0 = ff2(q[2], kb.x, a0);  a0 = ff2(q[3], kb.y, a0);
            u64 a1 = mul2(q[4], ka.x); a1 = ff2(q[5], ka.y, a1);
            a1 = ff2(q[6], kb.x, a1);  a1 = ff2(q[7], kb.y, a1);
            float2 f0 = un2(a0), f1 = un2(a1);
            u64 pp = pk2(f0.x + f0.y, f1.x + f1.y);       // (half r0, half r1)
            float2 po = un2(shflx(pp, 1));                // partner's halves
            float2 pl = un2(pp);
            float e0 = __expf(pl.x + po.x);               // full score r0
            float e1 = __expf(pl.y + po.y);               // full score r1
            esum2 = add2(esum2, pk2(e0, e1));
            const ulonglong2* vr = (const ulonglong2*)(sV + s * 20 + nh * 8);
            ulonglong2 va = vr[0], vb = vr[1];
            u64 e20 = dup2(e0), e21 = dup2(e1);
            o[0] = ff2(e20, va.x, o[0]); o[1] = ff2(e20, va.y, o[1]);
            o[2] = ff2(e20, vb.x, o[2]); o[3] = ff2(e20, vb.y, o[3]);
            o[4] = ff2(e21, va.x, o[4]); o[5] = ff2(e21, va.y, o[5]);
            o[6] = ff2(e21, vb.x, o[6]); o[7] = ff2(e21, vb.y, o[7]);
        }

        // --- epilogue, all in registers ---
        // c[n] = sum_r (Ao[r]/esum_r) * o[r][n]; lane holds partial over its 2 r
        float2 es = un2(esum2);
        float c0 = __fdividef(ao2.x, es.x);
        float c1 = __fdividef(ao2.y, es.y);
        u64 c20 = dup2(c0), c21 = dup2(c1);
        u64 cc[4];
        #pragma unroll
        for (int i = 0; i < 4; i++)
            cc[i] = ff2(c21, o[4 + i], mul2(c20, o[i]));
        // reduce over the 16 rp values (lanes sharing nh): xor lanes 2,4,8,16
        #pragma unroll
        for (int m = 2; m <= 16; m <<= 1) {
            #pragma unroll
            for (int i = 0; i < 4; i++)
                cc[i] = add2(cc[i], shflx(cc[i], m));
        }
        // cc now = z[n] for n = nh*8 + {0..7} (replicated across rp)
        // R = tanh(z) via 1 - 2/(exp(2z)+1)  (accurate to ~1e-6)
        float R2[8];
        float htot = 0.0f;
        #pragma unroll
        for (int i = 0; i < 4; i++) {
            float2 z = un2(cc[i]);
            float t0 = 1.0f - __fdividef(2.0f, __expf(2.0f * z.x) + 1.0f);
            float t1 = 1.0f - __fdividef(2.0f, __expf(2.0f * z.y) + 1.0f);
            R2[2 * i]     = t0 * t0;
            R2[2 * i + 1] = t1 * t1;
            htot += R2[2 * i] + R2[2 * i + 1];
        }
        float tot = htot + __shfl_xor_sync(0xffffffffu, htot, 1);

        // write: lanes 0 (n 0..7) and 1 (n 8..15) emit the 16-float row
        if (lane < 2) {
            const int ii = b & 15;
            float w0[8];
            #pragma unroll
            for (int e = 0; e < 8; e++) {
                int j = nh * 8 + e;
                w0[e] = (j == ii) ? tot : -R2[e];
            }
            float4* op = (float4*)(out + (size_t)b * 16 + nh * 8);
            op[0] = make_float4(w0[0], w0[1], w0[2], w0[3]);
            op[1] = make_float4(w0[4], w0[5], w0[6], w0[7]);
        }
        __syncwarp();   // sK/sV dead before next iteration's x staging
    }
}

extern "C" void kernel_launch(void* const* d_in, const int* in_sizes, int n_in,
                              void* d_out, int out_size)
{
    const float* x  = (const float*)d_in[0];
    const float* L  = (const float*)d_in[1];
    const float* Aq = (const float*)d_in[2];
    const float* Ak = (const float*)d_in[3];
    const float* Av = (const float*)d_in[4];
    const float* Ao = (const float*)d_in[5];
    float* out = (float*)d_out;

    int B = in_sizes[0] / (64 * 16);          // 65536
    int blocks = B / (WARPS * NB);            // 2048

    cudaFuncSetAttribute(att_mask_kernel,
                         cudaFuncAttributeMaxDynamicSharedMemorySize, SMEM_BYTES);
    att_mask_kernel<<<blocks, WARPS * 32, SMEM_BYTES>>>(x, L, Aq, Ak, Av, Ao, out);
}

// round 13
// speedup vs baseline: 1.0480x; 1.0020x over previous
#include <cuda_runtime.h>

// ---------------------------------------------------------------------------
// Att_mask, one warp per batch item. R11 -> R12: L1 crossbar is return-byte
// bound (broadcasts deliver 32x redundant bytes). New lane mapping:
//   lane = (rp, nh): rp = lane>>1 in [0,16) -> rows {2rp, 2rp+1},
//                    nh = lane&1            -> n-half [nh*8, nh*8+8)
// Each lane reads only HALF an x row / K row / V row (32B instead of 64B),
// halving broadcast traffic in both the projection and the scores loop.
// Cross-half score sums via one u64 shfl_xor(1) per s. Epilogue reduction
// entirely in registers via shfl_xor tree (no shared round-trip).
// ---------------------------------------------------------------------------

typedef unsigned long long u64;

__device__ __forceinline__ u64 ff2(u64 a, u64 b, u64 c) {
    u64 d; asm("fma.rn.f32x2 %0, %1, %2, %3;" : "=l"(d) : "l"(a), "l"(b), "l"(c)); return d;
}
__device__ __forceinline__ u64 mul2(u64 a, u64 b) {
    u64 d; asm("mul.rn.f32x2 %0, %1, %2;" : "=l"(d) : "l"(a), "l"(b)); return d;
}
__device__ __forceinline__ u64 add2(u64 a, u64 b) {
    u64 d; asm("add.rn.f32x2 %0, %1, %2;" : "=l"(d) : "l"(a), "l"(b)); return d;
}
__device__ __forceinline__ u64 dup2(float a) {
    u64 d; asm("mov.b64 %0, {%1, %1};" : "=l"(d) : "f"(a)); return d;
}
__device__ __forceinline__ float2 un2(u64 a) {
    float2 f; asm("mov.b64 {%0, %1}, %2;" : "=f"(f.x), "=f"(f.y) : "l"(a)); return f;
}
__device__ __forceinline__ u64 pk2(float x, float y) {
    u64 d; asm("mov.b64 %0, {%1, %2};" : "=l"(d) : "f"(x), "f"(y)); return d;
}
__device__ __forceinline__ float tanh_approx(float x) {
    float y; asm("tanh.approx.f32 %0, %1;" : "=f"(y) : "f"(x)); return y;
}
__device__ __forceinline__ u64 shflx(u64 v, int m) {
    return __shfl_xor_sync(0xffffffffu, v, m);
}

static constexpr int WARPS = 8;     // warps per block
static constexpr int NB    = 4;     // batch items per warp
// shared layout (floats):
//   sA: [64][16] records of 8 floats: (Aq[2rp][d],Aq[2rp+1][d],
//        Ak[2rp][d],Ak[2rp+1][d],Av[2rp][d],Av[2rp+1][d],0,0)  = 8192 floats
//   per warp: 1280-float region: x[64][16] (1024) during projection,
//        then aliased by K rows [32] stride 20 (640) + V rows (640)
static constexpr int A_FLOATS  = 64 * 16 * 8;                      // 8192
static constexpr int PW_FLOATS = 1280;
static constexpr int SMEM_BYTES = (A_FLOATS + WARPS * PW_FLOATS) * 4;  // 73728

__global__ void __launch_bounds__(WARPS * 32, 2)
att_mask_kernel(const float* __restrict__ x, const float* __restrict__ L,
                const float* __restrict__ Aq, const float* __restrict__ Ak,
                const float* __restrict__ Av, const float* __restrict__ Ao,
                float* __restrict__ out)
{
    extern __shared__ float smem[];
    float* sA = smem;

    const int tid = threadIdx.x;

    // Pack A per (d, rp): one 32B record read by the two lanes of the pair.
    for (int i = tid; i < 1024; i += WARPS * 32) {
        int d = i >> 4, rp = i & 15;
        float* p = sA + i * 8;
        p[0] = Aq[(2 * rp) * 64 + d];  p[1] = Aq[(2 * rp + 1) * 64 + d];
        p[2] = Ak[(2 * rp) * 64 + d];  p[3] = Ak[(2 * rp + 1) * 64 + d];
        p[4] = Av[(2 * rp) * 64 + d];  p[5] = Av[(2 * rp + 1) * 64 + d];
        p[6] = 0.f;                    p[7] = 0.f;
    }
    __syncthreads();

    const int w    = tid >> 5;
    const int lane = tid & 31;
    const int rp   = lane >> 1;      // row pair: rows 2rp, 2rp+1
    const int nh   = lane & 1;       // n-half: columns nh*8 .. nh*8+7

    float* sx = smem + A_FLOATS + w * PW_FLOATS;   // [64][16] during projection
    float* sK = sx;                                // aliased: 32 rows, stride 20
    float* sV = sx + 640;

    const float2 ao2 = ((const float2*)Ao)[rp];    // Ao[2rp], Ao[2rp+1]

    for (int jj = 0; jj < NB; jj++) {
        const int b = (blockIdx.x * WARPS + w) * NB + jj;

        // --- stage x_b (64x16 fp32 = 4KB contiguous) into shared ---
        {
            const float4* xg = (const float4*)(x + (size_t)b * 1024);
            float4* xs = (float4*)sx;
            #pragma unroll
            for (int i = 0; i < 8; i++)
                xs[i * 32 + lane] = xg[i * 32 + lane];
        }

        // --- num_neighbors from L[b,0,:] (values are exactly 0.0/1.0) ---
        float Lv = (lane < 16) ? L[(size_t)b * 256 + lane] : 0.0f;
        unsigned msk = __ballot_sync(0xffffffffu, Lv >= 1.0f);
        float rs = rsqrtf((float)(__popc(msk) + 1));
        __syncwarp();

        // --- projections: lane accumulates rows {2rp,2rp+1} x half-n ---
        // q/k/v[0..3] = row 2rp (4 u64 = 8 n-vals), [4..7] = row 2rp+1
        u64 q[8], k[8], v[8];
        #pragma unroll
        for (int p = 0; p < 8; p++) { q[p] = 0ull; k[p] = 0ull; v[p] = 0ull; }

        const float* xbase = sx + nh * 8;
        #pragma unroll 4
        for (int d = 0; d < 64; d++) {
            const ulonglong2* xr = (const ulonglong2*)(xbase + d * 16);
            ulonglong2 xa = xr[0], xb = xr[1];                 // 32B half-row
            const float* ap = sA + (d * 16 + rp) * 8;
            const float4 qk  = *(const float4*)ap;             // aq0,aq1,ak0,ak1
            const float2 avv = *(const float2*)(ap + 4);       // av0,av1
            u64 aq0 = dup2(qk.x),  aq1 = dup2(qk.y);
            u64 ak0 = dup2(qk.z),  ak1 = dup2(qk.w);
            u64 av0 = dup2(avv.x), av1 = dup2(avv.y);
            q[0] = ff2(aq0, xa.x, q[0]); q[1] = ff2(aq0, xa.y, q[1]);
            q[2] = ff2(aq0, xb.x, q[2]); q[3] = ff2(aq0, xb.y, q[3]);
            q[4] = ff2(aq1, xa.x, q[4]); q[5] = ff2(aq1, xa.y, q[5]);
            q[6] = ff2(aq1, xb.x, q[6]); q[7] = ff2(aq1, xb.y, q[7]);
            k[0] = ff2(ak0, xa.x, k[0]); k[1] = ff2(ak0, xa.y, k[1]);
            k[2] = ff2(ak0, xb.x, k[2]); k[3] = ff2(ak0, xb.y, k[3]);
            k[4] = ff2(ak1, xa.x, k[4]); k[5] = ff2(ak1, xa.y, k[5]);
            k[6] = ff2(ak1, xb.x, k[6]); k[7] = ff2(ak1, xb.y, k[7]);
            v[0] = ff2(av0, xa.x, v[0]); v[1] = ff2(av0, xa.y, v[1]);
            v[2] = ff2(av0, xb.x, v[2]); v[3] = ff2(av0, xb.y, v[3]);
            v[4] = ff2(av1, xa.x, v[4]); v[5] = ff2(av1, xa.y, v[5]);
            v[6] = ff2(av1, xb.x, v[6]); v[7] = ff2(av1, xb.y, v[7]);
        }
        __syncwarp();   // done reading sx; safe to overwrite with K/V

        // --- tanh; fold 1/sqrt(nn) into Q; publish K,V half-rows ---
        {
            u64 rs2 = dup2(rs);
            #pragma unroll
            for (int p = 0; p < 8; p++) {
                float2 fq = un2(q[p]);
                q[p] = mul2(pk2(tanh_approx(fq.x), tanh_approx(fq.y)), rs2);
                float2 fk = un2(k[p]);
                k[p] = pk2(tanh_approx(fk.x), tanh_approx(fk.y));
                float2 fv = un2(v[p]);
                v[p] = pk2(tanh_approx(fv.x), tanh_approx(fv.y));
            }
            const int r0 = 2 * rp, r1 = 2 * rp + 1;
            ulonglong2* k0p = (ulonglong2*)(sK + r0 * 20 + nh * 8);
            k0p[0] = make_ulonglong2(k[0], k[1]);
            k0p[1] = make_ulonglong2(k[2], k[3]);
            ulonglong2* k1p = (ulonglong2*)(sK + r1 * 20 + nh * 8);
            k1p[0] = make_ulonglong2(k[4], k[5]);
            k1p[1] = make_ulonglong2(k[6], k[7]);
            ulonglong2* v0p = (ulonglong2*)(sV + r0 * 20 + nh * 8);
            v0p[0] = make_ulonglong2(v[0], v[1]);
            v0p[1] = make_ulonglong2(v[2], v[3]);
            ulonglong2* v1p = (ulonglong2*)(sV + r1 * 20 + nh * 8);
            v1p[0] = make_ulonglong2(v[4], v[5]);
            v1p[1] = make_ulonglong2(v[6], v[7]);
        }
        __syncwarp();

        // --- fused scores + softmax numerator + o accumulation ---
        // |score| <= 16 -> exp safe without max subtraction.
        u64 o[8];
        #pragma unroll
        for (int p = 0; p < 8; p++) o[p] = 0ull;
        u64 esum2 = 0ull;    // packed (esum_r0, esum_r1)

        #pragma unroll 8
        for (int s = 0; s < 32; s++) {
            const ulonglong2* kr = (const ulonglong2*)(sK + s * 20 + nh * 8);
            ulonglong2 ka = kr[0], kb = kr[1];
            u64 a0 = mul2(q[0], ka.x); a0 = ff2(q[1], ka.y, a0);
            a0 = ff2(q[2], kb.x, a0);  a0 = ff2(q[3], kb.y, a0);
            u64 a1 = mul2(q[4], ka.x); a1 = ff2(q[5], ka.y, a1);
            a1 = ff2(q[6], kb.x, a1);  a1 = ff2(q[7], kb.y, a1);
            float2 f0 = un2(a0), f1 = un2(a1);
            u64 pp = pk2(f0.x + f0.y, f1.x + f1.y);       // (half r0, half r1)
            float2 po = un2(shflx(pp, 1));                // partner's halves
            float2 pl = un2(pp);
            float e0 = __expf(pl.x + po.x);               // full score r0
            float e1 = __expf(pl.y + po.y);               // full score r1
            esum2 = add2(esum2, pk2(e0, e1));
            const ulonglong2* vr = (const ulonglong2*)(sV + s * 20 + nh * 8);
            ulonglong2 va = vr[0], vb = vr[1];
            u64 e20 = dup2(e0), e21 = dup2(e1);
            o[0] = ff2(e20, va.x, o[0]); o[1] = ff2(e20, va.y, o[1]);
            o[2] = ff2(e20, vb.x, o[2]); o[3] = ff2(e20, vb.y, o[3]);
            o[4] = ff2(e21, va.x, o[4]); o[5] = ff2(e21, va.y, o[5]);
            o[6] = ff2(e21, vb.x, o[6]); o[7] = ff2(e21, vb.y, o[7]);
        }

        // --- epilogue, all in registers ---
        // c[n] = sum_r (Ao[r]/esum_r) * o[r][n]; lane holds partial over its 2 r
        float2 es = un2(esum2);
        float c0 = __fdividef(ao2.x, es.x);
        float c1 = __fdividef(ao2.y, es.y);
        u64 c20 = dup2(c0), c21 = dup2(c1);
        u64 cc[4];
        #pragma unroll
        for (int i = 0; i < 4; i++)
            cc[i] = ff2(c21, o[4 + i], mul2(c20, o[i]));
        // reduce over the 16 rp values (lanes sharing nh): xor lanes 2,4,8,16
        #pragma unroll
        for (int m = 2; m <= 16; m <<= 1) {
            #pragma unroll
            for (int i = 0; i < 4; i++)
                cc[i] = add2(cc[i], shflx(cc[i], m));
        }
        // cc now = z[n] for n = nh*8 + {0..7} (replicated across rp)
        // R = tanh(z) via 1 - 2/(exp(2z)+1)  (accurate to ~1e-6)
        float R2[8];
        float htot = 0.0f;
        #pragma unroll
        for (int i = 0; i < 4; i++) {
            float2 z = un2(cc[i]);
            float t0 = 1.0f - __fdividef(2.0f, __expf(2.0f * z.x) + 1.0f);
            float t1 = 1.0f - __fdividef(2.0f, __expf(2.0f * z.y) + 1.0f);
            R2[2 * i]     = t0 * t0;
            R2[2 * i + 1] = t1 * t1;
            htot += R2[2 * i] + R2[2 * i + 1];
        }
        float tot = htot + __shfl_xor_sync(0xffffffffu, htot, 1);

        // write: lanes 0 (n 0..7) and 1 (n 8..15) emit the 16-float row
        if (lane < 2) {
            const int ii = b & 15;
            float w0[8];
            #pragma unroll
            for (int e = 0; e < 8; e++) {
                int j = nh * 8 + e;
                w0[e] = (j == ii) ? tot : -R2[e];
            }
            float4* op = (float4*)(out + (size_t)b * 16 + nh * 8);
            op[0] = make_float4(w0[0], w0[1], w0[2], w0[3]);
            op[1] = make_float4(w0[4], w0[5], w0[6], w0[7]);
        }
        __syncwarp();   // sK/sV dead before next iteration's x staging
    }
}

extern "C" void kernel_launch(void* const* d_in, const int* in_sizes, int n_in,
                              void* d_out, int out_size)
{
    const float* x  = (const float*)d_in[0];
    const float* L  = (const float*)d_in[1];
    const float* Aq = (const float*)d_in[2];
    const float* Ak = (const float*)d_in[3];
    const float* Av = (const float*)d_in[4];
    const float* Ao = (const float*)d_in[5];
    float* out = (float*)d_out;

    int B = in_sizes[0] / (64 * 16);          // 65536
    int blocks = B / (WARPS * NB);            // 2048

    cudaFuncSetAttribute(att_mask_kernel,
                         cudaFuncAttributeMaxDynamicSharedMemorySize, SMEM_BYTES);
    att_mask_kernel<<<blocks, WARPS * 32, SMEM_BYTES>>>(x, L, Aq, Ak, Av, Ao, out);
}